// round 3
// baseline (speedup 1.0000x reference)
#include <cuda_runtime.h>
#include <math.h>

#define B_  8
#define S_  2048
#define D_  768
#define BS_ (B_*S_)          // 16384
#define SD_ (S_*D_)          // 1572864
#define CTX_ELEMS (B_*S_*D_) // 12582912
#define ATT_ELEMS ((size_t)B_*S_*S_) // 33554432

// Scratch (allocation-free rule: __device__ globals)
__device__ float g_q[BS_*D_];
__device__ float g_k[BS_*D_];
__device__ float g_v[BS_*D_];
__device__ float g_rowsum[BS_];

// ---------------------------------------------------------------------------
// Projection GEMM: Y[M=16384][768] = X[M][768] @ W[768][768]^T + bias
// sel: 0->g_q, 1->g_k, 2->g_v
// ---------------------------------------------------------------------------
__global__ __launch_bounds__(256, 2)
void proj_kernel(const float* __restrict__ X, const float* __restrict__ W,
                 const float* __restrict__ bias, int sel)
{
    const int K = D_;
    const int N = D_;
    __shared__ float As[16][132];
    __shared__ float Bs[16][132];

    float* Y = (sel == 0) ? g_q : (sel == 1) ? g_k : g_v;

    const int tid = threadIdx.x;
    const int tx = tid & 15, ty = tid >> 4;
    const int rowBase = blockIdx.y * 128;
    const int colBase = blockIdx.x * 128;

    float acc[8][8];
#pragma unroll
    for (int i = 0; i < 8; i++)
#pragma unroll
        for (int j = 0; j < 8; j++) acc[i][j] = 0.0f;

    for (int k0 = 0; k0 < K; k0 += 16) {
#pragma unroll
        for (int it = 0; it < 2; it++) {
            int i = tid + it * 256;          // 0..511
            int r = i >> 2, kq = i & 3;
            float4 a = *(const float4*)&X[(size_t)(rowBase + r) * K + k0 + kq * 4];
            As[kq*4+0][r] = a.x; As[kq*4+1][r] = a.y;
            As[kq*4+2][r] = a.z; As[kq*4+3][r] = a.w;
            float4 b = *(const float4*)&W[(size_t)(colBase + r) * K + k0 + kq * 4];
            Bs[kq*4+0][r] = b.x; Bs[kq*4+1][r] = b.y;
            Bs[kq*4+2][r] = b.z; Bs[kq*4+3][r] = b.w;
        }
        __syncthreads();
#pragma unroll
        for (int k = 0; k < 16; k++) {
            float a[8], b[8];
            *(float4*)&a[0] = *(float4*)&As[k][ty * 8];
            *(float4*)&a[4] = *(float4*)&As[k][ty * 8 + 4];
            *(float4*)&b[0] = *(float4*)&Bs[k][tx * 8];
            *(float4*)&b[4] = *(float4*)&Bs[k][tx * 8 + 4];
#pragma unroll
            for (int i = 0; i < 8; i++)
#pragma unroll
                for (int j = 0; j < 8; j++) acc[i][j] = fmaf(a[i], b[j], acc[i][j]);
        }
        __syncthreads();
    }

#pragma unroll
    for (int i = 0; i < 8; i++) {
        int r = rowBase + ty * 8 + i;
#pragma unroll
        for (int j = 0; j < 8; j++) {
            int c = colBase + tx * 8 + j;
            Y[(size_t)r * N + c] = acc[i][j] + bias[c];
        }
    }
}

// ---------------------------------------------------------------------------
// Logits GEMM per batch: L[q][k] = Q[q]·K[k] / sqrt(768); masked -> 0,
// else exp(); write UNNORMALIZED weights. Row sums done by rowsum_kernel
// (deterministic, no atomics). Mask arrives as int32 (harness converts bool).
// grid (16,16,8)
// ---------------------------------------------------------------------------
__global__ __launch_bounds__(256, 2)
void logits_kernel(const int* __restrict__ mask, float* __restrict__ attn)
{
    const int K = D_;
    const int b = blockIdx.z;
    const float* Q  = g_q + (size_t)b * SD_;
    const float* Kp = g_k + (size_t)b * SD_;
    float* attn_b = attn + (size_t)b * S_ * S_;
    const int* mask_b = mask + (size_t)b * S_ * S_;

    __shared__ float As[16][132];
    __shared__ float Bs[16][132];

    const int tid = threadIdx.x;
    const int tx = tid & 15, ty = tid >> 4;
    const int rowBase = blockIdx.y * 128;
    const int colBase = blockIdx.x * 128;

    float acc[8][8];
#pragma unroll
    for (int i = 0; i < 8; i++)
#pragma unroll
        for (int j = 0; j < 8; j++) acc[i][j] = 0.0f;

    for (int k0 = 0; k0 < K; k0 += 16) {
#pragma unroll
        for (int it = 0; it < 2; it++) {
            int i = tid + it * 256;
            int r = i >> 2, kq = i & 3;
            float4 a = *(const float4*)&Q[(size_t)(rowBase + r) * K + k0 + kq * 4];
            As[kq*4+0][r] = a.x; As[kq*4+1][r] = a.y;
            As[kq*4+2][r] = a.z; As[kq*4+3][r] = a.w;
            float4 bb = *(const float4*)&Kp[(size_t)(colBase + r) * K + k0 + kq * 4];
            Bs[kq*4+0][r] = bb.x; Bs[kq*4+1][r] = bb.y;
            Bs[kq*4+2][r] = bb.z; Bs[kq*4+3][r] = bb.w;
        }
        __syncthreads();
#pragma unroll
        for (int k = 0; k < 16; k++) {
            float a[8], b[8];
            *(float4*)&a[0] = *(float4*)&As[k][ty * 8];
            *(float4*)&a[4] = *(float4*)&As[k][ty * 8 + 4];
            *(float4*)&b[0] = *(float4*)&Bs[k][tx * 8];
            *(float4*)&b[4] = *(float4*)&Bs[k][tx * 8 + 4];
#pragma unroll
            for (int i = 0; i < 8; i++)
#pragma unroll
                for (int j = 0; j < 8; j++) acc[i][j] = fmaf(a[i], b[j], acc[i][j]);
        }
        __syncthreads();
    }

    const float inv_scale = 0.03608439182435161f; // 1/sqrt(768)
#pragma unroll
    for (int i = 0; i < 8; i++) {
        int r = rowBase + ty * 8 + i;
        float w[8];
        const int* mrow = &mask_b[(size_t)r * S_ + colBase + tx * 8];
        int4 m0 = *(const int4*)&mrow[0];
        int4 m1 = *(const int4*)&mrow[4];
        w[0] = m0.x ? 0.0f : expf(acc[i][0] * inv_scale);
        w[1] = m0.y ? 0.0f : expf(acc[i][1] * inv_scale);
        w[2] = m0.z ? 0.0f : expf(acc[i][2] * inv_scale);
        w[3] = m0.w ? 0.0f : expf(acc[i][3] * inv_scale);
        w[4] = m1.x ? 0.0f : expf(acc[i][4] * inv_scale);
        w[5] = m1.y ? 0.0f : expf(acc[i][5] * inv_scale);
        w[6] = m1.z ? 0.0f : expf(acc[i][6] * inv_scale);
        w[7] = m1.w ? 0.0f : expf(acc[i][7] * inv_scale);
        *(float4*)&attn_b[(size_t)r * S_ + colBase + tx * 8]     = *(float4*)&w[0];
        *(float4*)&attn_b[(size_t)r * S_ + colBase + tx * 8 + 4] = *(float4*)&w[4];
    }
}

// ---------------------------------------------------------------------------
// Deterministic row sums: one 256-thread block per row of attn [16384 rows].
// Fixed-order strided accumulation + fixed-shape tree reduction -> bitwise
// identical on every replay (no atomics).
// ---------------------------------------------------------------------------
__global__ __launch_bounds__(256)
void rowsum_kernel(const float* __restrict__ attn)
{
    __shared__ float red[256];
    const int row = blockIdx.x;               // 0..BS_-1
    const float* p = attn + (size_t)row * S_;
    const int tid = threadIdx.x;

    float s = 0.0f;
    // 2048 elems / 256 threads = 8 per thread; float4 strided, fixed order
#pragma unroll
    for (int it = 0; it < 2; it++) {
        float4 v = *(const float4*)&p[(tid + it * 256) * 4];
        s += (v.x + v.y) + (v.z + v.w);
    }
    red[tid] = s;
    __syncthreads();
#pragma unroll
    for (int o = 128; o >= 1; o >>= 1) {
        if (tid < o) red[tid] = red[tid] + red[tid + o];
        __syncthreads();
    }
    if (tid == 0) g_rowsum[row] = red[0];
}

// ---------------------------------------------------------------------------
// Context GEMM per batch: C[q][d] = sum_k Wu[q][k] * V[k][d], then /rowsum.
// A = unnormalized attn [2048][2048], B = V [2048][768] (k-major, NOT transposed)
// grid (6,16,8)
// ---------------------------------------------------------------------------
__global__ __launch_bounds__(256, 2)
void ctx_kernel(const float* __restrict__ attn, float* __restrict__ ctx)
{
    const int K = S_;
    const int N = D_;
    const int b = blockIdx.z;
    const float* A = attn + (size_t)b * S_ * S_;
    const float* V = g_v + (size_t)b * SD_;

    __shared__ float As[16][132];
    __shared__ float Bs[16][132];

    const int tid = threadIdx.x;
    const int tx = tid & 15, ty = tid >> 4;
    const int rowBase = blockIdx.y * 128;
    const int colBase = blockIdx.x * 128;

    float acc[8][8];
#pragma unroll
    for (int i = 0; i < 8; i++)
#pragma unroll
        for (int j = 0; j < 8; j++) acc[i][j] = 0.0f;

    for (int k0 = 0; k0 < K; k0 += 16) {
#pragma unroll
        for (int it = 0; it < 2; it++) {
            int i = tid + it * 256;
            int r = i >> 2, kq = i & 3;
            float4 a = *(const float4*)&A[(size_t)(rowBase + r) * K + k0 + kq * 4];
            As[kq*4+0][r] = a.x; As[kq*4+1][r] = a.y;
            As[kq*4+2][r] = a.z; As[kq*4+3][r] = a.w;
            // B (V) is [K][N]: load row-of-N directly, no transpose
            int kk = i >> 5, nq = i & 31;
            float4 bb = *(const float4*)&V[(size_t)(k0 + kk) * N + colBase + nq * 4];
            *(float4*)&Bs[kk][nq * 4] = bb;
        }
        __syncthreads();
#pragma unroll
        for (int k = 0; k < 16; k++) {
            float a[8], b[8];
            *(float4*)&a[0] = *(float4*)&As[k][ty * 8];
            *(float4*)&a[4] = *(float4*)&As[k][ty * 8 + 4];
            *(float4*)&b[0] = *(float4*)&Bs[k][tx * 8];
            *(float4*)&b[4] = *(float4*)&Bs[k][tx * 8 + 4];
#pragma unroll
            for (int i = 0; i < 8; i++)
#pragma unroll
                for (int j = 0; j < 8; j++) acc[i][j] = fmaf(a[i], b[j], acc[i][j]);
        }
        __syncthreads();
    }

#pragma unroll
    for (int i = 0; i < 8; i++) {
        int r = rowBase + ty * 8 + i;
        float invr = 1.0f / g_rowsum[b * S_ + r];
        float o[8];
#pragma unroll
        for (int j = 0; j < 8; j++) o[j] = acc[i][j] * invr;
        float* dst = &ctx[((size_t)b * S_ + r) * D_ + colBase + tx * 8];
        *(float4*)&dst[0] = *(float4*)&o[0];
        *(float4*)&dst[4] = *(float4*)&o[4];
    }
}

// Normalize attn weights in place: attn[b][q][k] /= rowsum[b*S+q]
__global__ void norm_attn_kernel(float* __restrict__ attn)
{
    size_t i = (size_t)blockIdx.x * 256 + threadIdx.x;  // float4 index
    if (i < ATT_ELEMS / 4) {
        float4 v = ((float4*)attn)[i];
        size_t lin = i * 4;
        float inv = 1.0f / g_rowsum[lin / S_];
        v.x *= inv; v.y *= inv; v.z *= inv; v.w *= inv;
        ((float4*)attn)[i] = v;
    }
}

extern "C" void kernel_launch(void* const* d_in, const int* in_sizes, int n_in,
                              void* d_out, int out_size)
{
    (void)in_sizes; (void)n_in; (void)out_size;
    const float* query = (const float*)d_in[0];
    const float* key   = (const float*)d_in[1];
    const float* value = (const float*)d_in[2];
    const int*   mask  = (const int*)d_in[3];   // bool -> int32 (harness conversion)
    const float* Wq = (const float*)d_in[4];
    const float* bq = (const float*)d_in[5];
    const float* Wk = (const float*)d_in[6];
    const float* bk = (const float*)d_in[7];
    const float* Wv = (const float*)d_in[8];
    const float* bv = (const float*)d_in[9];

    float* out  = (float*)d_out;
    float* ctx  = out;                 // [B,S,D]
    float* attn = out + CTX_ELEMS;     // [B,S,S]

    dim3 gproj(6, 128);
    proj_kernel<<<gproj, 256>>>(query, Wq, bq, 0);
    proj_kernel<<<gproj, 256>>>(key,   Wk, bk, 1);
    proj_kernel<<<gproj, 256>>>(value, Wv, bv, 2);

    dim3 glog(16, 16, 8);
    logits_kernel<<<glog, 256>>>(mask, attn);

    rowsum_kernel<<<BS_, 256>>>(attn);

    dim3 gctx(6, 16, 8);
    ctx_kernel<<<gctx, 256>>>(attn, ctx);

    norm_attn_kernel<<<(unsigned)(ATT_ELEMS / 4 / 256), 256>>>(attn);
}

// round 5
// speedup vs baseline: 2.1670x; 2.1670x over previous
// R5: identical resubmission of the R4 tf32-mma kernel — R4 failed on a
// broker/container infra error with no metric signal (same signature as R1,
// which cleared on resubmit). No design change until the bench speaks.
#include <cuda_runtime.h>
#include <math.h>

#define B_  8
#define S_  2048
#define D_  768
#define BS_ (B_*S_)          // 16384
#define SD_ (S_*D_)          // 1572864
#define CTX_ELEMS (B_*S_*D_) // 12582912
#define ATT_ELEMS ((size_t)B_*S_*S_) // 33554432

// Scratch (allocation-free rule: __device__ globals)
__device__ float g_q[BS_*D_];
__device__ float g_k[BS_*D_];
__device__ float g_v[BS_*D_];
__device__ float g_rowsum[BS_];

// ---------------------------------------------------------------------------
// tf32 helpers
// ---------------------------------------------------------------------------
__device__ __forceinline__ unsigned f2tf32(float f) {
    unsigned r;
    asm("cvt.rna.tf32.f32 %0, %1;" : "=r"(r) : "f"(f));
    return r;
}

__device__ __forceinline__ void mma_tf32(float* c,
                                         unsigned a0, unsigned a1, unsigned a2, unsigned a3,
                                         unsigned b0, unsigned b1) {
    asm volatile(
        "mma.sync.aligned.m16n8k8.row.col.f32.tf32.tf32.f32 "
        "{%0,%1,%2,%3},{%4,%5,%6,%7},{%8,%9},{%0,%1,%2,%3};"
        : "+f"(c[0]), "+f"(c[1]), "+f"(c[2]), "+f"(c[3])
        : "r"(a0), "r"(a1), "r"(a2), "r"(a3), "r"(b0), "r"(b1));
}

// Shared-tile stride: bank(r,c) = (36*r + c) mod 32 = (4r+c) mod 32 -> the
// (lane/4, lane%4) fragment-read pattern is conflict-free.
#define LDA_ 36

// Warp-level 64x32 tf32 MMA over one 32-deep K-chunk.
// As: [128][LDA_] row(m)-major by k; Bs: [128][LDA_] row(n)-major by k.
__device__ __forceinline__ void warp_mma_chunk(const float (*As)[LDA_],
                                               const float (*Bs)[LDA_],
                                               float acc[4][4][4],
                                               int wm, int wn, int lane) {
    const int gp = lane >> 2;      // 0..7
    const int qd = lane & 3;       // 0..3
#pragma unroll
    for (int kk = 0; kk < 4; kk++) {
        const int kb = kk * 8;
        unsigned a[4][4], b[4][2];
#pragma unroll
        for (int mi = 0; mi < 4; mi++) {
            const int rb = wm * 64 + mi * 16;
            a[mi][0] = f2tf32(As[rb + gp][kb + qd]);
            a[mi][1] = f2tf32(As[rb + 8 + gp][kb + qd]);
            a[mi][2] = f2tf32(As[rb + gp][kb + 4 + qd]);
            a[mi][3] = f2tf32(As[rb + 8 + gp][kb + 4 + qd]);
        }
#pragma unroll
        for (int ni = 0; ni < 4; ni++) {
            const int cb = wn * 32 + ni * 8;
            b[ni][0] = f2tf32(Bs[cb + gp][kb + qd]);
            b[ni][1] = f2tf32(Bs[cb + gp][kb + 4 + qd]);
        }
#pragma unroll
        for (int mi = 0; mi < 4; mi++)
#pragma unroll
            for (int ni = 0; ni < 4; ni++)
                mma_tf32(acc[mi][ni], a[mi][0], a[mi][1], a[mi][2], a[mi][3],
                         b[ni][0], b[ni][1]);
    }
}

// ---------------------------------------------------------------------------
// Projection GEMM: Y[16384][768] = X @ W^T + bias.  sel: 0->g_q,1->g_k,2->g_v
// grid (6, 128), 256 threads
// ---------------------------------------------------------------------------
__global__ __launch_bounds__(256, 2)
void proj_kernel(const float* __restrict__ X, const float* __restrict__ W,
                 const float* __restrict__ bias, int sel)
{
    __shared__ float As[128][LDA_];
    __shared__ float Bs[128][LDA_];
    float* Y = (sel == 0) ? g_q : (sel == 1) ? g_k : g_v;

    const int tid = threadIdx.x;
    const int lane = tid & 31, w = tid >> 5;
    const int wm = w & 1, wn = w >> 1;
    const int rowBase = blockIdx.y * 128;
    const int colBase = blockIdx.x * 128;

    float acc[4][4][4];
#pragma unroll
    for (int mi = 0; mi < 4; mi++)
#pragma unroll
        for (int ni = 0; ni < 4; ni++)
#pragma unroll
            for (int t = 0; t < 4; t++) acc[mi][ni][t] = 0.0f;

    for (int k0 = 0; k0 < D_; k0 += 32) {
#pragma unroll
        for (int it = 0; it < 4; it++) {
            int idx = tid + it * 256;            // 0..1023
            int r = idx >> 3, c4 = idx & 7;
            float4 va = *(const float4*)&X[(size_t)(rowBase + r) * D_ + k0 + c4 * 4];
            As[r][c4*4+0] = va.x; As[r][c4*4+1] = va.y;
            As[r][c4*4+2] = va.z; As[r][c4*4+3] = va.w;
            float4 vb = *(const float4*)&W[(size_t)(colBase + r) * D_ + k0 + c4 * 4];
            Bs[r][c4*4+0] = vb.x; Bs[r][c4*4+1] = vb.y;
            Bs[r][c4*4+2] = vb.z; Bs[r][c4*4+3] = vb.w;
        }
        __syncthreads();
        warp_mma_chunk(As, Bs, acc, wm, wn, lane);
        __syncthreads();
    }

    const int gp = lane >> 2, qd = lane & 3;
#pragma unroll
    for (int mi = 0; mi < 4; mi++) {
        int r0 = rowBase + wm * 64 + mi * 16 + gp;
#pragma unroll
        for (int ni = 0; ni < 4; ni++) {
            int c = colBase + wn * 32 + ni * 8 + qd * 2;
            float b0 = bias[c], b1 = bias[c + 1];
            *(float2*)&Y[(size_t)r0 * D_ + c] =
                make_float2(acc[mi][ni][0] + b0, acc[mi][ni][1] + b1);
            *(float2*)&Y[(size_t)(r0 + 8) * D_ + c] =
                make_float2(acc[mi][ni][2] + b0, acc[mi][ni][3] + b1);
        }
    }
}

// ---------------------------------------------------------------------------
// Logits: per batch QK^T/sqrt(D), mask->0 else exp, write unnormalized.
// grid (16, 16, 8)
// ---------------------------------------------------------------------------
__global__ __launch_bounds__(256, 2)
void logits_kernel(const int* __restrict__ mask, float* __restrict__ attn)
{
    __shared__ float As[128][LDA_];
    __shared__ float Bs[128][LDA_];

    const int b = blockIdx.z;
    const float* Q  = g_q + (size_t)b * SD_;
    const float* Kp = g_k + (size_t)b * SD_;
    float* attn_b = attn + (size_t)b * S_ * S_;
    const int* mask_b = mask + (size_t)b * S_ * S_;

    const int tid = threadIdx.x;
    const int lane = tid & 31, w = tid >> 5;
    const int wm = w & 1, wn = w >> 1;
    const int rowBase = blockIdx.y * 128;
    const int colBase = blockIdx.x * 128;

    float acc[4][4][4];
#pragma unroll
    for (int mi = 0; mi < 4; mi++)
#pragma unroll
        for (int ni = 0; ni < 4; ni++)
#pragma unroll
            for (int t = 0; t < 4; t++) acc[mi][ni][t] = 0.0f;

    for (int k0 = 0; k0 < D_; k0 += 32) {
#pragma unroll
        for (int it = 0; it < 4; it++) {
            int idx = tid + it * 256;
            int r = idx >> 3, c4 = idx & 7;
            float4 va = *(const float4*)&Q[(size_t)(rowBase + r) * D_ + k0 + c4 * 4];
            As[r][c4*4+0] = va.x; As[r][c4*4+1] = va.y;
            As[r][c4*4+2] = va.z; As[r][c4*4+3] = va.w;
            float4 vb = *(const float4*)&Kp[(size_t)(colBase + r) * D_ + k0 + c4 * 4];
            Bs[r][c4*4+0] = vb.x; Bs[r][c4*4+1] = vb.y;
            Bs[r][c4*4+2] = vb.z; Bs[r][c4*4+3] = vb.w;
        }
        __syncthreads();
        warp_mma_chunk(As, Bs, acc, wm, wn, lane);
        __syncthreads();
    }

    const float inv_scale = 0.03608439182435161f; // 1/sqrt(768)
    const int gp = lane >> 2, qd = lane & 3;
#pragma unroll
    for (int mi = 0; mi < 4; mi++) {
        int r0 = rowBase + wm * 64 + mi * 16 + gp;
        int r1 = r0 + 8;
#pragma unroll
        for (int ni = 0; ni < 4; ni++) {
            int c = colBase + wn * 32 + ni * 8 + qd * 2;
            int2 m0 = *(const int2*)&mask_b[(size_t)r0 * S_ + c];
            int2 m1 = *(const int2*)&mask_b[(size_t)r1 * S_ + c];
            float2 w0, w1;
            w0.x = m0.x ? 0.0f : expf(acc[mi][ni][0] * inv_scale);
            w0.y = m0.y ? 0.0f : expf(acc[mi][ni][1] * inv_scale);
            w1.x = m1.x ? 0.0f : expf(acc[mi][ni][2] * inv_scale);
            w1.y = m1.y ? 0.0f : expf(acc[mi][ni][3] * inv_scale);
            *(float2*)&attn_b[(size_t)r0 * S_ + c] = w0;
            *(float2*)&attn_b[(size_t)r1 * S_ + c] = w1;
        }
    }
}

// ---------------------------------------------------------------------------
// Deterministic row sums (no atomics; bitwise identical on every replay)
// ---------------------------------------------------------------------------
__global__ __launch_bounds__(256)
void rowsum_kernel(const float* __restrict__ attn)
{
    __shared__ float red[256];
    const int row = blockIdx.x;               // 0..BS_-1
    const float* p = attn + (size_t)row * S_;
    const int tid = threadIdx.x;

    float s = 0.0f;
#pragma unroll
    for (int it = 0; it < 2; it++) {
        float4 v = *(const float4*)&p[(tid + it * 256) * 4];
        s += (v.x + v.y) + (v.z + v.w);
    }
    red[tid] = s;
    __syncthreads();
#pragma unroll
    for (int o = 128; o >= 1; o >>= 1) {
        if (tid < o) red[tid] = red[tid] + red[tid + o];
        __syncthreads();
    }
    if (tid == 0) g_rowsum[row] = red[0];
}

// ---------------------------------------------------------------------------
// Context: C[q][d] = (sum_k Wu[q][k] V[k][d]) / rowsum[q].  grid (6,16,8)
// V tile transposed on the STS path into Bs[n][k].
// ---------------------------------------------------------------------------
__global__ __launch_bounds__(256, 2)
void ctx_kernel(const float* __restrict__ attn, float* __restrict__ ctx)
{
    __shared__ float As[128][LDA_];
    __shared__ float Bs[128][LDA_];

    const int b = blockIdx.z;
    const float* A = attn + (size_t)b * S_ * S_;
    const float* V = g_v + (size_t)b * SD_;

    const int tid = threadIdx.x;
    const int lane = tid & 31, w = tid >> 5;
    const int wm = w & 1, wn = w >> 1;
    const int rowBase = blockIdx.y * 128;
    const int colBase = blockIdx.x * 128;

    float acc[4][4][4];
#pragma unroll
    for (int mi = 0; mi < 4; mi++)
#pragma unroll
        for (int ni = 0; ni < 4; ni++)
#pragma unroll
            for (int t = 0; t < 4; t++) acc[mi][ni][t] = 0.0f;

    for (int k0 = 0; k0 < S_; k0 += 32) {
#pragma unroll
        for (int it = 0; it < 4; it++) {
            int idx = tid + it * 256;
            int r = idx >> 3, c4 = idx & 7;
            float4 va = *(const float4*)&A[(size_t)(rowBase + r) * S_ + k0 + c4 * 4];
            As[r][c4*4+0] = va.x; As[r][c4*4+1] = va.y;
            As[r][c4*4+2] = va.z; As[r][c4*4+3] = va.w;
            // V is [k][n]: transpose into Bs[n][k]
            int kk = idx >> 5, n4 = idx & 31;
            float4 vb = *(const float4*)&V[(size_t)(k0 + kk) * D_ + colBase + n4 * 4];
            Bs[n4*4+0][kk] = vb.x; Bs[n4*4+1][kk] = vb.y;
            Bs[n4*4+2][kk] = vb.z; Bs[n4*4+3][kk] = vb.w;
        }
        __syncthreads();
        warp_mma_chunk(As, Bs, acc, wm, wn, lane);
        __syncthreads();
    }

    const int gp = lane >> 2, qd = lane & 3;
#pragma unroll
    for (int mi = 0; mi < 4; mi++) {
        int r0 = rowBase + wm * 64 + mi * 16 + gp;
        int r1 = r0 + 8;
        float inv0 = 1.0f / g_rowsum[b * S_ + r0];
        float inv1 = 1.0f / g_rowsum[b * S_ + r1];
#pragma unroll
        for (int ni = 0; ni < 4; ni++) {
            int c = colBase + wn * 32 + ni * 8 + qd * 2;
            *(float2*)&ctx[((size_t)b * S_ + r0) * D_ + c] =
                make_float2(acc[mi][ni][0] * inv0, acc[mi][ni][1] * inv0);
            *(float2*)&ctx[((size_t)b * S_ + r1) * D_ + c] =
                make_float2(acc[mi][ni][2] * inv1, acc[mi][ni][3] * inv1);
        }
    }
}

// Normalize attn weights in place: attn[b][q][k] /= rowsum[b*S+q]
__global__ void norm_attn_kernel(float* __restrict__ attn)
{
    size_t i = (size_t)blockIdx.x * 256 + threadIdx.x;  // float4 index
    if (i < ATT_ELEMS / 4) {
        float4 v = ((float4*)attn)[i];
        size_t lin = i * 4;
        float inv = 1.0f / g_rowsum[lin / S_];
        v.x *= inv; v.y *= inv; v.z *= inv; v.w *= inv;
        ((float4*)attn)[i] = v;
    }
}

extern "C" void kernel_launch(void* const* d_in, const int* in_sizes, int n_in,
                              void* d_out, int out_size)
{
    (void)in_sizes; (void)n_in; (void)out_size;
    const float* query = (const float*)d_in[0];
    const float* key   = (const float*)d_in[1];
    const float* value = (const float*)d_in[2];
    const int*   mask  = (const int*)d_in[3];   // bool -> int32 (harness conversion)
    const float* Wq = (const float*)d_in[4];
    const float* bq = (const float*)d_in[5];
    const float* Wk = (const float*)d_in[6];
    const float* bk = (const float*)d_in[7];
    const float* Wv = (const float*)d_in[8];
    const float* bv = (const float*)d_in[9];

    float* out  = (float*)d_out;
    float* ctx  = out;                 // [B,S,D]
    float* attn = out + CTX_ELEMS;     // [B,S,S]

    dim3 gproj(6, 128);
    proj_kernel<<<gproj, 256>>>(query, Wq, bq, 0);
    proj_kernel<<<gproj, 256>>>(key,   Wk, bk, 1);
    proj_kernel<<<gproj, 256>>>(value, Wv, bv, 2);

    dim3 glog(16, 16, 8);
    logits_kernel<<<glog, 256>>>(mask, attn);

    rowsum_kernel<<<BS_, 256>>>(attn);

    dim3 gctx(6, 16, 8);
    ctx_kernel<<<gctx, 256>>>(attn, ctx);

    norm_attn_kernel<<<(unsigned)(ATT_ELEMS / 4 / 256), 256>>>(attn);
}